// round 13
// baseline (speedup 1.0000x reference)
#include <cuda_runtime.h>
#include <cuda_bf16.h>

// ============================================================================
// MaskFunctionHaar, v6: global-LUT split with high-parallelism apply.
// Output depends only on M = floor(t*1024) in [0,1024).
//   Kernel A (prep): 32 blocks x 32 threads, one M per thread -> global
//     1024 x float4 LUT (weights in registers, float4 broadcast loads).
//   Kernel B (apply): 512 blocks x 256 threads, ONE scalar sample per thread.
//     No SMEM, no barrier: coalesced LDG t -> one L2-resident LUT gather ->
//     3 scalar stores (contiguous 384B per warp). 4096 warps chip-wide
//     (~7 per SMSP) hide the two chained memory latencies.
// ============================================================================

__device__ float4 g_lut[1024];

__global__ __launch_bounds__(32, 1) void haar_prep6_kernel(
    const float* __restrict__ W1, const float* __restrict__ b1,
    const float* __restrict__ W2, const float* __restrict__ b2,
    const float* __restrict__ W3, const float* __restrict__ b3) {
    const int M = blockIdx.x * 32 + threadIdx.x;   // 0..1023

    // ---- stage tail weights into registers (uniform float4 broadcasts) ----
    float w2[64];
#pragma unroll
    for (int i = 0; i < 16; ++i) {
        float4 v = __ldg((const float4*)W2 + i);
        w2[4 * i + 0] = v.x; w2[4 * i + 1] = v.y;
        w2[4 * i + 2] = v.z; w2[4 * i + 3] = v.w;
    }
    float w3[24];
#pragma unroll
    for (int i = 0; i < 6; ++i) {
        float4 v = __ldg((const float4*)W3 + i);
        w3[4 * i + 0] = v.x; w3[4 * i + 1] = v.y;
        w3[4 * i + 2] = v.z; w3[4 * i + 3] = v.w;
    }
    float bb2[8];
    {
        float4 v0 = __ldg((const float4*)b2);
        float4 v1 = __ldg((const float4*)b2 + 1);
        bb2[0] = v0.x; bb2[1] = v0.y; bb2[2] = v0.z; bb2[3] = v0.w;
        bb2[4] = v1.x; bb2[5] = v1.y; bb2[6] = v1.z; bb2[7] = v1.w;
    }
    float bb3[3];
    bb3[0] = __ldg(b3 + 0); bb3[1] = __ldg(b3 + 1); bb3[2] = __ldg(b3 + 2);

    // ---- layer 1: 10 Haar levels, 8 accumulators ----
    float P[8];
    {
        float4 v0 = __ldg((const float4*)b1);
        float4 v1 = __ldg((const float4*)b1 + 1);
        P[0] = v0.x; P[1] = v0.y; P[2] = v0.z; P[3] = v0.w;
        P[4] = v1.x; P[5] = v1.y; P[6] = v1.z; P[7] = v1.w;
    }
#pragma unroll
    for (int j = 0; j < 10; ++j) {
        int idx = (1 << j) - 1 + (M >> (10 - j));
        float s = ((M >> (9 - j)) & 1) ? -1.0f : 1.0f;
        const float4* row = (const float4*)(W1 + idx * 8);
        float4 a = __ldg(row);
        float4 c = __ldg(row + 1);
        P[0] = fmaf(s, a.x, P[0]); P[1] = fmaf(s, a.y, P[1]);
        P[2] = fmaf(s, a.z, P[2]); P[3] = fmaf(s, a.w, P[3]);
        P[4] = fmaf(s, c.x, P[4]); P[5] = fmaf(s, c.y, P[5]);
        P[6] = fmaf(s, c.z, P[6]); P[7] = fmaf(s, c.w, P[7]);
    }
#pragma unroll
    for (int h = 0; h < 8; ++h) P[h] = fmaxf(P[h], 0.0f);

    // ---- layer 2 ----
    float h2[8];
#pragma unroll
    for (int k = 0; k < 8; ++k) h2[k] = bb2[k];
#pragma unroll
    for (int h = 0; h < 8; ++h) {
        float x = P[h];
#pragma unroll
        for (int k = 0; k < 8; ++k) h2[k] = fmaf(x, w2[h * 8 + k], h2[k]);
    }
#pragma unroll
    for (int k = 0; k < 8; ++k) h2[k] = fmaxf(h2[k], 0.0f);

    // ---- layer 3 ----
    float o0 = bb3[0], o1 = bb3[1], o2 = bb3[2];
#pragma unroll
    for (int k = 0; k < 8; ++k) {
        float x = h2[k];
        o0 = fmaf(x, w3[k * 3 + 0], o0);
        o1 = fmaf(x, w3[k * 3 + 1], o1);
        o2 = fmaf(x, w3[k * 3 + 2], o2);
    }
    g_lut[M] = make_float4(o0, o1, o2, 0.0f);
}

__global__ __launch_bounds__(256, 1) void haar_apply6_kernel(
    const float* __restrict__ t, float* __restrict__ out, int n) {
    const int g = blockIdx.x * 256 + threadIdx.x;
    if (g >= n) return;

    float tv = __ldg(t + g);
    unsigned m = min((unsigned)(int)(tv * 1024.0f), 1023u);

    float4 r = __ldg((const float4*)g_lut + m);

    out[3 * g + 0] = r.x;
    out[3 * g + 1] = r.y;
    out[3 * g + 2] = r.z;
}

extern "C" void kernel_launch(void* const* d_in, const int* in_sizes, int n_in,
                              void* d_out, int out_size) {
    const float* t  = (const float*)d_in[0];
    const float* W1 = (const float*)d_in[1];
    const float* b1 = (const float*)d_in[2];
    const float* W2 = (const float*)d_in[3];
    const float* b2 = (const float*)d_in[4];
    const float* W3 = (const float*)d_in[5];
    const float* b3 = (const float*)d_in[6];
    float* out = (float*)d_out;

    int n = in_sizes[0];             // B*T = 131072

    haar_prep6_kernel<<<32, 32>>>(W1, b1, W2, b2, W3, b3);
    haar_apply6_kernel<<<(n + 255) / 256, 256>>>(t, out, n);
}

// round 15
// speedup vs baseline: 1.3029x; 1.3029x over previous
#include <cuda_runtime.h>
#include <cuda_bf16.h>

// ============================================================================
// MaskFunctionHaar, v7: global-LUT split + Programmatic Dependent Launch.
// Output depends only on M = floor(t*1024) in [0,1024).
//   Kernel A (prep): 32 blocks x 32 threads, one M per thread -> global
//     1024 x float4 LUT (weights in registers). Triggers programmatic
//     launch completion early.
//   Kernel B (apply): 512 blocks x 256 threads, one scalar sample each.
//     Launched with ProgrammaticStreamSerialization so it starts WHILE prep
//     runs: loads t + computes the index first, then
//     cudaGridDependencySynchronize() before reading the LUT.
// ============================================================================

__device__ float4 g_lut[1024];

__global__ __launch_bounds__(32, 1) void haar_prep7_kernel(
    const float* __restrict__ W1, const float* __restrict__ b1,
    const float* __restrict__ W2, const float* __restrict__ b2,
    const float* __restrict__ W3, const float* __restrict__ b3) {
    const int M = blockIdx.x * 32 + threadIdx.x;   // 0..1023

    // ---- stage tail weights into registers (uniform float4 broadcasts) ----
    float w2[64];
#pragma unroll
    for (int i = 0; i < 16; ++i) {
        float4 v = __ldg((const float4*)W2 + i);
        w2[4 * i + 0] = v.x; w2[4 * i + 1] = v.y;
        w2[4 * i + 2] = v.z; w2[4 * i + 3] = v.w;
    }
    float w3[24];
#pragma unroll
    for (int i = 0; i < 6; ++i) {
        float4 v = __ldg((const float4*)W3 + i);
        w3[4 * i + 0] = v.x; w3[4 * i + 1] = v.y;
        w3[4 * i + 2] = v.z; w3[4 * i + 3] = v.w;
    }
    float bb2[8];
    {
        float4 v0 = __ldg((const float4*)b2);
        float4 v1 = __ldg((const float4*)b2 + 1);
        bb2[0] = v0.x; bb2[1] = v0.y; bb2[2] = v0.z; bb2[3] = v0.w;
        bb2[4] = v1.x; bb2[5] = v1.y; bb2[6] = v1.z; bb2[7] = v1.w;
    }
    float bb3[3];
    bb3[0] = __ldg(b3 + 0); bb3[1] = __ldg(b3 + 1); bb3[2] = __ldg(b3 + 2);

    // ---- layer 1: 10 Haar levels, 8 accumulators ----
    float P[8];
    {
        float4 v0 = __ldg((const float4*)b1);
        float4 v1 = __ldg((const float4*)b1 + 1);
        P[0] = v0.x; P[1] = v0.y; P[2] = v0.z; P[3] = v0.w;
        P[4] = v1.x; P[5] = v1.y; P[6] = v1.z; P[7] = v1.w;
    }
#pragma unroll
    for (int j = 0; j < 10; ++j) {
        int idx = (1 << j) - 1 + (M >> (10 - j));
        float s = ((M >> (9 - j)) & 1) ? -1.0f : 1.0f;
        const float4* row = (const float4*)(W1 + idx * 8);
        float4 a = __ldg(row);
        float4 c = __ldg(row + 1);
        P[0] = fmaf(s, a.x, P[0]); P[1] = fmaf(s, a.y, P[1]);
        P[2] = fmaf(s, a.z, P[2]); P[3] = fmaf(s, a.w, P[3]);
        P[4] = fmaf(s, c.x, P[4]); P[5] = fmaf(s, c.y, P[5]);
        P[6] = fmaf(s, c.z, P[6]); P[7] = fmaf(s, c.w, P[7]);
    }
#pragma unroll
    for (int h = 0; h < 8; ++h) P[h] = fmaxf(P[h], 0.0f);

    // ---- layer 2 ----
    float h2[8];
#pragma unroll
    for (int k = 0; k < 8; ++k) h2[k] = bb2[k];
#pragma unroll
    for (int h = 0; h < 8; ++h) {
        float x = P[h];
#pragma unroll
        for (int k = 0; k < 8; ++k) h2[k] = fmaf(x, w2[h * 8 + k], h2[k]);
    }
#pragma unroll
    for (int k = 0; k < 8; ++k) h2[k] = fmaxf(h2[k], 0.0f);

    // ---- layer 3 ----
    float o0 = bb3[0], o1 = bb3[1], o2 = bb3[2];
#pragma unroll
    for (int k = 0; k < 8; ++k) {
        float x = h2[k];
        o0 = fmaf(x, w3[k * 3 + 0], o0);
        o1 = fmaf(x, w3[k * 3 + 1], o1);
        o2 = fmaf(x, w3[k * 3 + 2], o2);
    }
    g_lut[M] = make_float4(o0, o1, o2, 0.0f);

#if __CUDA_ARCH__ >= 900
    // signal that dependent launches may proceed once our mem writes drain
    cudaTriggerProgrammaticLaunchCompletion();
#endif
}

__global__ __launch_bounds__(256, 1) void haar_apply7_kernel(
    const float* __restrict__ t, float* __restrict__ out, int n) {
    const int g = blockIdx.x * 256 + threadIdx.x;

    // Pre-dependency work: load t, compute the LUT index.
    float tv = 0.0f;
    if (g < n) tv = __ldg(t + g);
    unsigned m = min((unsigned)(int)(tv * 1024.0f), 1023u);

#if __CUDA_ARCH__ >= 900
    // Wait until prep's writes to g_lut are visible.
    cudaGridDependencySynchronize();
#endif

    if (g < n) {
        float4 r = __ldg((const float4*)g_lut + m);
        out[3 * g + 0] = r.x;
        out[3 * g + 1] = r.y;
        out[3 * g + 2] = r.z;
    }
}

extern "C" void kernel_launch(void* const* d_in, const int* in_sizes, int n_in,
                              void* d_out, int out_size) {
    const float* t  = (const float*)d_in[0];
    const float* W1 = (const float*)d_in[1];
    const float* b1 = (const float*)d_in[2];
    const float* W2 = (const float*)d_in[3];
    const float* b2 = (const float*)d_in[4];
    const float* W3 = (const float*)d_in[5];
    const float* b3 = (const float*)d_in[6];
    float* out = (float*)d_out;

    int n = in_sizes[0];             // B*T = 131072

    // prep: plain launch
    haar_prep7_kernel<<<32, 32>>>(W1, b1, W2, b2, W3, b3);

    // apply: programmatic dependent launch (overlaps with prep)
    cudaLaunchConfig_t cfg = {};
    cfg.gridDim  = dim3((n + 255) / 256, 1, 1);
    cfg.blockDim = dim3(256, 1, 1);
    cfg.dynamicSmemBytes = 0;
    cfg.stream = 0;
    cudaLaunchAttribute attrs[1];
    attrs[0].id = cudaLaunchAttributeProgrammaticStreamSerialization;
    attrs[0].val.programmaticStreamSerializationAllowed = 1;
    cfg.attrs = attrs;
    cfg.numAttrs = 1;

    cudaError_t err = cudaLaunchKernelEx(&cfg, haar_apply7_kernel, t, out, n);
    if (err != cudaSuccess) {
        // fallback: plain serialized launch
        haar_apply7_kernel<<<(n + 255) / 256, 256>>>(t, out, n);
    }
}